// round 13
// baseline (speedup 1.0000x reference)
#include <cuda_runtime.h>
#include <cuda_fp16.h>
#include <mma.h>

using namespace nvcuda;

#define NN 100000
#define NC 5000
#define CAP_SIM 128
#define CAP_MEN 320
#define CAP_REL 128

// ---------------- scratch (device globals; no allocs allowed) ----------------
__device__ __half2 g_xn0h[NN * 32];
__device__ __half2 g_xn1h[NN * 32];
__device__ __half2 g_aggNh[NN * 32];
__device__ float g_xc0[NC * 64];
__device__ __half2 g_xc0h[NC * 32];
__device__ float g_xc1[NC * 64];
__device__ __half2 g_xc1h[NC * 32];
__device__ __half2 g_aggCmh[NC * 32];
__device__ __half2 g_aggCm2h[NC * 32];   // layer-2 mentions mean (separate: avoids WAR with comp1)
__device__ __half2 g_aggCrh[NC * 32];
__device__ int g_bufS[NN * CAP_SIM];
__device__ int g_bufM[NC * CAP_MEN];
__device__ int g_bufR[NC * CAP_REL];
__device__ int g_cntS[NN];
__device__ int g_cntM[NC];
__device__ int g_cntR[NC];

__device__ __forceinline__ unsigned h2u(__half2 h) {
    return *reinterpret_cast<unsigned*>(&h);
}

// ---------------- zero adjacency counters ----------------
__global__ void zero_cnt_kernel() {
    int i = blockIdx.x * blockDim.x + threadIdx.x;
    if (i < NN) g_cntS[i] = 0;
    if (i < NC) { g_cntM[i] = 0; g_cntR[i] = 0; }
}

// ---------------- build capped-bucket CSR for all 3 relations ----------------
__global__ void fill_kernel(const int* __restrict__ es_src, const int* __restrict__ es_dst,
                            const int* __restrict__ mn_src, const int* __restrict__ mn_dst,
                            const int* __restrict__ rl_src, const int* __restrict__ rl_dst,
                            int Es, int Em, int Er) {
    int i = blockIdx.x * blockDim.x + threadIdx.x;
    if (i < Es) {
        int d = __ldg(es_dst + i);
        int p = atomicAdd(&g_cntS[d], 1);
        if (p < CAP_SIM) g_bufS[d * CAP_SIM + p] = __ldg(es_src + i);
    }
    if (i < Em) {
        int d = __ldg(mn_dst + i);
        int p = atomicAdd(&g_cntM[d], 1);
        if (p < CAP_MEN) g_bufM[d * CAP_MEN + p] = __ldg(mn_src + i);
    }
    if (i < Er) {
        int d = __ldg(rl_dst + i);
        int p = atomicAdd(&g_cntR[d], 1);
        if (p < CAP_REL) g_bufR[d * CAP_REL + p] = __ldg(rl_src + i);
    }
}

// ---------------- gather-mean fp16 -> fp16: warp per row (rows [row_base, row_end)) ----------------
__global__ void __launch_bounds__(256) gatherh_kernel(const __half2* __restrict__ xt,
                                                      const int* __restrict__ buf,
                                                      const int* __restrict__ cnt,
                                                      __half2* __restrict__ agg,
                                                      int row_base, int row_end, int cap) {
    int gw = row_base + ((blockIdx.x * 256 + threadIdx.x) >> 5);
    int lane = threadIdx.x & 31;
    if (gw >= row_end) return;
    int n = cnt[gw];
    if (n > cap) n = cap;
    const int* lst = buf + gw * cap;
    float2 a0 = {0.f, 0.f}, a1 = {0.f, 0.f}, a2 = {0.f, 0.f}, a3 = {0.f, 0.f};
    int n4 = n >> 2;
    for (int i = 0; i < n4; i++) {
        int4 s = __ldg((const int4*)lst + i);
        float2 v0 = __half22float2(__ldg(xt + s.x * 32 + lane));
        float2 v1 = __half22float2(__ldg(xt + s.y * 32 + lane));
        float2 v2 = __half22float2(__ldg(xt + s.z * 32 + lane));
        float2 v3 = __half22float2(__ldg(xt + s.w * 32 + lane));
        a0.x += v0.x; a0.y += v0.y;
        a1.x += v1.x; a1.y += v1.y;
        a2.x += v2.x; a2.y += v2.y;
        a3.x += v3.x; a3.y += v3.y;
    }
    for (int e = n4 << 2; e < n; e++) {
        int s = __ldg(lst + e);
        float2 v = __half22float2(__ldg(xt + s * 32 + lane));
        a0.x += v.x; a0.y += v.y;
    }
    float inv = 1.f / (float)(n < 1 ? 1 : n);
    agg[gw * 32 + lane] = __floats2half2_rn((a0.x + a1.x + a2.x + a3.x) * inv,
                                            (a0.y + a1.y + a2.y + a3.y) * inv);
}

// ---------------- input GEMM (news): wmma tf32, 128x64 tile, 8 warps ----------------
__global__ void __launch_bounds__(256) gemm_news0_kernel(const float* __restrict__ X,
                                                         const float* __restrict__ W,
                                                         const float* __restrict__ b) {
    extern __shared__ float sm[];
    float* As = sm;            // 128 x 36 (stride-padded)
    float* Bs = sm + 4608;     // 32 x 68
    float* Cs = sm;            // 128 x 64 (reuse after mainloop)
    float* xs384 = sm + 8192;  // 128
    const int tid = threadIdx.x;
    const int wid = tid >> 5;
    const int row0 = blockIdx.x * 128;

    if (tid < 128) {
        int row = row0 + tid;
        xs384[tid] = (row < NN) ? __ldg(X + row * 385 + 384) : 0.f;
    }

    wmma::fragment<wmma::accumulator, 16, 16, 8, float> cfr[4];
#pragma unroll
    for (int c = 0; c < 4; c++) wmma::fill_fragment(cfr[c], 0.f);

    for (int kc = 0; kc < 384; kc += 32) {
#pragma unroll 4
        for (int idx = tid; idx < 4096; idx += 256) {
            int r = idx >> 5, k = idx & 31;
            int row = row0 + r;
            As[r * 36 + k] = (row < NN) ? X[row * 385 + kc + k] : 0.f;
        }
#pragma unroll 2
        for (int idx = tid; idx < 2048; idx += 256) {
            int k = idx >> 6, n = idx & 63;
            Bs[k * 68 + n] = W[(kc + k) * 64 + n];
        }
        __syncthreads();
#pragma unroll
        for (int k0 = 0; k0 < 32; k0 += 8) {
            wmma::fragment<wmma::matrix_a, 16, 16, 8, wmma::precision::tf32, wmma::row_major> af;
            wmma::load_matrix_sync(af, As + wid * 16 * 36 + k0, 36);
#pragma unroll
            for (int i = 0; i < af.num_elements; i++) af.x[i] = wmma::__float_to_tf32(af.x[i]);
#pragma unroll
            for (int c = 0; c < 4; c++) {
                wmma::fragment<wmma::matrix_b, 16, 16, 8, wmma::precision::tf32, wmma::row_major> bf;
                wmma::load_matrix_sync(bf, Bs + k0 * 68 + c * 16, 68);
#pragma unroll
                for (int i = 0; i < bf.num_elements; i++) bf.x[i] = wmma::__float_to_tf32(bf.x[i]);
                wmma::mma_sync(cfr[c], af, bf, cfr[c]);
            }
        }
        __syncthreads();
    }

#pragma unroll
    for (int c = 0; c < 4; c++)
        wmma::store_matrix_sync(Cs + wid * 16 * 64 + c * 16, cfr[c], 64, wmma::mem_row_major);
    __syncthreads();

    int r = tid >> 1, half = tid & 1;
    int row = row0 + r;
    if (row < NN) {
        float x384 = xs384[r];
        const float* w384 = W + 384 * 64 + half * 32;
        const float* crow = Cs + r * 64 + half * 32;
        const float* brow = b + half * 32;
        unsigned hv[16];
#pragma unroll
        for (int j = 0; j < 16; j++) {
            float v0 = fmaxf(crow[2 * j] + __ldg(brow + 2 * j) + x384 * __ldg(w384 + 2 * j), 0.f);
            float v1 = fmaxf(crow[2 * j + 1] + __ldg(brow + 2 * j + 1) + x384 * __ldg(w384 + 2 * j + 1), 0.f);
            hv[j] = h2u(__floats2half2_rn(v0, v1));
        }
        uint4* outh = (uint4*)(g_xn0h + row * 32 + half * 16);
#pragma unroll
        for (int q = 0; q < 4; q++)
            outh[q] = make_uint4(hv[4 * q], hv[4 * q + 1], hv[4 * q + 2], hv[4 * q + 3]);
    }
}

// ---------------- input GEMM (company): warp-per-row ----------------
__global__ void __launch_bounds__(256) comp0_kernel(const float* __restrict__ Xc,
                                                    const float* __restrict__ W,
                                                    const float* __restrict__ b) {
    __shared__ float ws[24 * 64];
    __shared__ float bs[64];
    __shared__ float xrow[8][24];
    int tid = threadIdx.x, lane = tid & 31, w = tid >> 5;
    for (int i = tid; i < 24 * 64; i += 256) ws[i] = W[i];
    if (tid < 64) bs[tid] = b[tid];
    int row = blockIdx.x * 8 + w;
    if (row < NC && lane < 24) xrow[w][lane] = Xc[row * 24 + lane];
    __syncthreads();
    if (row >= NC) return;
    float2 acc = make_float2(bs[2 * lane], bs[2 * lane + 1]);
#pragma unroll
    for (int k = 0; k < 24; k++) {
        float xv = xrow[w][k];
        float2 wv = ((const float2*)(ws + k * 64))[lane];
        acc.x += xv * wv.x;
        acc.y += xv * wv.y;
    }
    float2 o = make_float2(fmaxf(acc.x, 0.f), fmaxf(acc.y, 0.f));
    ((float2*)(g_xc0 + row * 64))[lane] = o;
    g_xc0h[row * 32 + lane] = __floats2half2_rn(o.x, o.y);
}

// ---------------- layer-1 news update: fp16 wmma dual-GEMM + LN, fp16 out (block-offset) ----------------
__global__ void __launch_bounds__(256) news_update_kernel(
    const float* __restrict__ Wl, const float* __restrict__ bl,
    const float* __restrict__ Wr, const float* __restrict__ gam,
    const float* __restrict__ bet, int blk_base) {
    extern __shared__ float smf[];
    __half* Asm = (__half*)smf;              // 128 x 72 (agg)
    __half* Bsm = Asm + 128 * 72;            // 128 x 72 (xn0)
    float* Cs = smf;                         // 128 x 64 fp32 (reuses A/B region)
    __half* Wlm = Bsm + 128 * 72;            // 64 x 72
    __half* Wrm = Wlm + 64 * 72;             // 64 x 72
    const int tid = threadIdx.x;
    const int wid = tid >> 5;
    const int row0 = (blk_base + blockIdx.x) * 128;

#pragma unroll
    for (int idx = tid; idx < 1024; idx += 256) {
        int r = idx >> 3, q = idx & 7;
        int grow = row0 + r;
        uint4 va = make_uint4(0u, 0u, 0u, 0u), vb = va;
        if (grow < NN) {
            va = __ldg((const uint4*)(g_aggNh + grow * 32) + q);
            vb = __ldg((const uint4*)(g_xn0h + grow * 32) + q);
        }
        *(uint4*)(Asm + r * 72 + q * 8) = va;
        *(uint4*)(Bsm + r * 72 + q * 8) = vb;
    }
#pragma unroll
    for (int idx = tid; idx < 4096; idx += 256) {
        int k = idx >> 6, n = idx & 63;
        Wlm[k * 72 + n] = __float2half(Wl[idx]);
        Wrm[k * 72 + n] = __float2half(Wr[idx]);
    }
    __syncthreads();

    wmma::fragment<wmma::accumulator, 16, 16, 16, float> cfr[4];
#pragma unroll
    for (int c = 0; c < 4; c++) wmma::fill_fragment(cfr[c], 0.f);

#pragma unroll
    for (int k0 = 0; k0 < 64; k0 += 16) {
        wmma::fragment<wmma::matrix_a, 16, 16, 16, __half, wmma::row_major> afA, afB;
        wmma::load_matrix_sync(afA, Asm + wid * 16 * 72 + k0, 72);
        wmma::load_matrix_sync(afB, Bsm + wid * 16 * 72 + k0, 72);
#pragma unroll
        for (int c = 0; c < 4; c++) {
            wmma::fragment<wmma::matrix_b, 16, 16, 16, __half, wmma::row_major> bfL, bfR;
            wmma::load_matrix_sync(bfL, Wlm + k0 * 72 + c * 16, 72);
            wmma::load_matrix_sync(bfR, Wrm + k0 * 72 + c * 16, 72);
            wmma::mma_sync(cfr[c], afA, bfL, cfr[c]);
            wmma::mma_sync(cfr[c], afB, bfR, cfr[c]);
        }
    }
    __syncthreads();
#pragma unroll
    for (int c = 0; c < 4; c++)
        wmma::store_matrix_sync(Cs + wid * 16 * 64 + c * 16, cfr[c], 64, wmma::mem_row_major);
    __syncthreads();

    int r = tid >> 1, half = tid & 1;
    int row = row0 + r;
    float v[32];
    const float* crow = Cs + r * 64 + half * 32;
    const float* blh = bl + half * 32;
    float ssum = 0.f;
#pragma unroll
    for (int j = 0; j < 32; j++) {
        v[j] = fmaxf(crow[j] + __ldg(blh + j), 0.f);
        ssum += v[j];
    }
    ssum += __shfl_xor_sync(0xffffffffu, ssum, 1);
    float m = ssum * (1.f / 64.f);
    float var = 0.f;
#pragma unroll
    for (int j = 0; j < 32; j++) { float d = v[j] - m; var += d * d; }
    var += __shfl_xor_sync(0xffffffffu, var, 1);
    float s = rsqrtf(var * (1.f / 64.f) + 1e-5f);
    if (row < NN) {
        const float* gmh = gam + half * 32;
        const float* bth = bet + half * 32;
        unsigned hv[16];
#pragma unroll
        for (int j = 0; j < 16; j++) {
            float o0 = (v[2 * j] - m) * s * __ldg(gmh + 2 * j) + __ldg(bth + 2 * j);
            float o1 = (v[2 * j + 1] - m) * s * __ldg(gmh + 2 * j + 1) + __ldg(bth + 2 * j + 1);
            hv[j] = h2u(__floats2half2_rn(o0, o1));
        }
        uint4* outh = (uint4*)(g_xn1h + row * 32 + half * 16);
#pragma unroll
        for (int q = 0; q < 4; q++)
            outh[q] = make_uint4(hv[4 * q], hv[4 * q + 1], hv[4 * q + 2], hv[4 * q + 3]);
    }
}

// ---------------- layer-1 company update: warp-per-row ----------------
__global__ void __launch_bounds__(256) comp1_kernel(const float* __restrict__ Wl,
                                                    const float* __restrict__ bl,
                                                    const float* __restrict__ Wr,
                                                    const float* __restrict__ gam,
                                                    const float* __restrict__ bet) {
    extern __shared__ float sm[];
    float* wl1 = sm;            // 4096
    float* wl2 = sm + 4096;     // 4096
    float* wrs = sm + 8192;     // 4096 = Wr1 + Wr2
    float* bsum = sm + 12288;   // 64
    float* stg = sm + 12352;    // 8 warps * 192
    int tid = threadIdx.x, lane = tid & 31, w = tid >> 5;
    for (int i = tid; i < 4096; i += 256) {
        wl1[i] = Wl[4096 + i];
        wl2[i] = Wl[8192 + i];
        wrs[i] = Wr[4096 + i] + Wr[8192 + i];
    }
    if (tid < 64) bsum[tid] = bl[64 + tid] + bl[128 + tid];
    int row = blockIdx.x * 8 + w;
    float* S = stg + w * 192;
    if (row < NC) {
        ((float2*)S)[lane] = __half22float2(__ldg(g_aggCmh + row * 32 + lane));
        ((float2*)(S + 64))[lane] = __half22float2(__ldg(g_aggCrh + row * 32 + lane));
        ((float2*)(S + 128))[lane] = ((const float2*)(g_xc0 + row * 64))[lane];
    }
    __syncthreads();
    if (row >= NC) return;
    float2 acc = make_float2(bsum[2 * lane], bsum[2 * lane + 1]);
#pragma unroll 8
    for (int k = 0; k < 64; k++) {
        float am = S[k], ar = S[64 + k], xk = S[128 + k];
        float2 w1 = ((const float2*)(wl1 + k * 64))[lane];
        float2 w2 = ((const float2*)(wl2 + k * 64))[lane];
        float2 w3 = ((const float2*)(wrs + k * 64))[lane];
        acc.x += am * w1.x + ar * w2.x + xk * w3.x;
        acc.y += am * w1.y + ar * w2.y + xk * w3.y;
    }
    float v0 = fmaxf(acc.x + S[128 + 2 * lane], 0.f);
    float v1 = fmaxf(acc.y + S[128 + 2 * lane + 1], 0.f);
    float ssum = v0 + v1;
#pragma unroll
    for (int o = 16; o > 0; o >>= 1) ssum += __shfl_xor_sync(0xffffffffu, ssum, o);
    float m = ssum * (1.f / 64.f);
    float d0 = v0 - m, d1 = v1 - m;
    float vs = d0 * d0 + d1 * d1;
#pragma unroll
    for (int o = 16; o > 0; o >>= 1) vs += __shfl_xor_sync(0xffffffffu, vs, o);
    float s = rsqrtf(vs * (1.f / 64.f) + 1e-5f);
    float2 o2;
    o2.x = d0 * s * __ldg(gam + 2 * lane) + __ldg(bet + 2 * lane);
    o2.y = d1 * s * __ldg(gam + 2 * lane + 1) + __ldg(bet + 2 * lane + 1);
    ((float2*)(g_xc1 + row * 64))[lane] = o2;
    g_xc1h[row * 32 + lane] = __floats2half2_rn(o2.x, o2.y);
}

// ---------------- layer-2 company + classifier: warp-per-row (on2 dead in reference) ----------------
__global__ void __launch_bounds__(256) compF_kernel(const float* __restrict__ Wl,
                                                    const float* __restrict__ bl,
                                                    const float* __restrict__ Wr,
                                                    const float* __restrict__ W1,
                                                    const float* __restrict__ b1,
                                                    const float* __restrict__ W2,
                                                    const float* __restrict__ b2,
                                                    float* __restrict__ out) {
    extern __shared__ float sm[];
    float* wl1 = sm;             // 4096
    float* wl2 = sm + 4096;      // 4096
    float* wrs = sm + 8192;      // 4096
    float* bsum = sm + 12288;    // 64
    float* w1s = sm + 12352;     // 2048
    float* b1s = sm + 14400;     // 32
    float* w2s = sm + 14432;     // 32
    float* stg = sm + 14464;     // 8 * 192
    float* cst = sm + 14464 + 1536;  // 8 * 64
    int tid = threadIdx.x, lane = tid & 31, w = tid >> 5;
    for (int i = tid; i < 4096; i += 256) {
        wl1[i] = Wl[4096 + i];
        wl2[i] = Wl[8192 + i];
        wrs[i] = Wr[4096 + i] + Wr[8192 + i];
    }
    for (int i = tid; i < 2048; i += 256) w1s[i] = W1[i];
    if (tid < 64) bsum[tid] = bl[64 + tid] + bl[128 + tid];
    if (tid < 32) { b1s[tid] = b1[tid]; w2s[tid] = W2[tid]; }
    int row = blockIdx.x * 8 + w;
    float* S = stg + w * 192;
    if (row < NC) {
        ((float2*)S)[lane] = __half22float2(__ldg(g_aggCm2h + row * 32 + lane));
        ((float2*)(S + 64))[lane] = __half22float2(__ldg(g_aggCrh + row * 32 + lane));
        ((float2*)(S + 128))[lane] = ((const float2*)(g_xc1 + row * 64))[lane];
    }
    __syncthreads();
    if (row >= NC) return;
    float2 acc = make_float2(bsum[2 * lane], bsum[2 * lane + 1]);
#pragma unroll 8
    for (int k = 0; k < 64; k++) {
        float am = S[k], ar = S[64 + k], xk = S[128 + k];
        float2 w1 = ((const float2*)(wl1 + k * 64))[lane];
        float2 w2 = ((const float2*)(wl2 + k * 64))[lane];
        float2 w3 = ((const float2*)(wrs + k * 64))[lane];
        acc.x += am * w1.x + ar * w2.x + xk * w3.x;
        acc.y += am * w1.y + ar * w2.y + xk * w3.y;
    }
    float* C = cst + w * 64;
    C[2 * lane] = fmaxf(acc.x + S[128 + 2 * lane], 0.f);
    C[2 * lane + 1] = fmaxf(acc.y + S[128 + 2 * lane + 1], 0.f);
    __syncwarp();
    float h = b1s[lane];
#pragma unroll 8
    for (int j = 0; j < 64; j++) h += C[j] * w1s[j * 32 + lane];
    float o = fmaxf(h, 0.f) * w2s[lane];
#pragma unroll
    for (int off = 16; off > 0; off >>= 1) o += __shfl_xor_sync(0xffffffffu, o, off);
    if (lane == 0) out[row] = o + __ldg(b2);
}

// ---------------- host launch ----------------
extern "C" void kernel_launch(void* const* d_in, const int* in_sizes, int n_in,
                              void* d_out, int out_size) {
    const float* x_news  = (const float*)d_in[0];
    const float* x_comp  = (const float*)d_in[1];
    const int*   e_sim   = (const int*)d_in[2];
    const int*   men_src = (const int*)d_in[3];
    const int*   men_dst = (const int*)d_in[4];
    const int*   e_rel   = (const int*)d_in[5];
    const float* nw_W = (const float*)d_in[6];
    const float* nw_b = (const float*)d_in[7];
    const float* cw_W = (const float*)d_in[8];
    const float* cw_b = (const float*)d_in[9];
    const float* n1n_g = (const float*)d_in[10];
    const float* n1n_b = (const float*)d_in[11];
    const float* n1c_g = (const float*)d_in[12];
    const float* n1c_b = (const float*)d_in[13];
    const float* c1_Wl = (const float*)d_in[14];
    const float* c1_bl = (const float*)d_in[15];
    const float* c1_Wr = (const float*)d_in[16];
    const float* c2_Wl = (const float*)d_in[17];
    const float* c2_bl = (const float*)d_in[18];
    const float* c2_Wr = (const float*)d_in[19];
    const float* cls_W1 = (const float*)d_in[20];
    const float* cls_b1 = (const float*)d_in[21];
    const float* cls_W2 = (const float*)d_in[22];
    const float* cls_b2 = (const float*)d_in[23];
    float* out = (float*)d_out;

    const int Es = in_sizes[2] / 2;
    const int Em = in_sizes[3];
    const int Er = in_sizes[5] / 2;
    const int* es_src = e_sim;
    const int* es_dst = e_sim + Es;
    const int* rl_src = e_rel;
    const int* rl_dst = e_rel + Er;

    __half2 *p_xn0h, *p_xn1h, *p_xc0h, *p_xc1h, *p_aggNh, *p_aggCmh, *p_aggCm2h, *p_aggCrh;
    int *p_bufS, *p_bufM, *p_bufR, *p_cntS, *p_cntM, *p_cntR;
    cudaGetSymbolAddress((void**)&p_xn0h, g_xn0h);
    cudaGetSymbolAddress((void**)&p_xn1h, g_xn1h);
    cudaGetSymbolAddress((void**)&p_xc0h, g_xc0h);
    cudaGetSymbolAddress((void**)&p_xc1h, g_xc1h);
    cudaGetSymbolAddress((void**)&p_aggNh, g_aggNh);
    cudaGetSymbolAddress((void**)&p_aggCmh, g_aggCmh);
    cudaGetSymbolAddress((void**)&p_aggCm2h, g_aggCm2h);
    cudaGetSymbolAddress((void**)&p_aggCrh, g_aggCrh);
    cudaGetSymbolAddress((void**)&p_bufS, g_bufS);
    cudaGetSymbolAddress((void**)&p_bufM, g_bufM);
    cudaGetSymbolAddress((void**)&p_bufR, g_bufR);
    cudaGetSymbolAddress((void**)&p_cntS, g_cntS);
    cudaGetSymbolAddress((void**)&p_cntM, g_cntM);
    cudaGetSymbolAddress((void**)&p_cntR, g_cntR);

    const int GEMM_SMEM = (8192 + 128) * 4;                       // 33280
    const int NU_SMEM = 2 * 128 * 72 * 2 + 2 * 64 * 72 * 2;       // 55296
    cudaFuncSetAttribute(news_update_kernel, cudaFuncAttributeMaxDynamicSharedMemorySize, NU_SMEM);
    cudaFuncSetAttribute(comp1_kernel, cudaFuncAttributeMaxDynamicSharedMemorySize, 56000);
    cudaFuncSetAttribute(compF_kernel, cudaFuncAttributeMaxDynamicSharedMemorySize, 66048);

    // ONE extra stream + FOUR events (the resource budget proven to pass teardown).
    // Events are RE-RECORDED for the pipeline handoffs — legal under stream capture:
    // each wait pairs with the most recent record in host issue order.
    cudaStream_t s2;
    cudaStreamCreateWithFlags(&s2, cudaStreamNonBlocking);
    cudaEvent_t e0, eA, eB, e3;
    cudaEventCreateWithFlags(&e0, cudaEventDisableTiming);
    cudaEventCreateWithFlags(&eA, cudaEventDisableTiming);
    cudaEventCreateWithFlags(&eB, cudaEventDisableTiming);
    cudaEventCreateWithFlags(&e3, cudaEventDisableTiming);

    // fork s2 from the capture origin stream
    cudaEventRecord(e0, 0);
    cudaStreamWaitEvent(s2, e0, 0);

    // branch 0 (origin): adjacency build
    zero_cnt_kernel<<<(NN + 255) / 256, 256>>>();
    fill_kernel<<<(Es + 255) / 256, 256>>>(es_src, es_dst, men_src, men_dst,
                                           rl_src, rl_dst, Es, Em, Er);
    cudaEventRecord(eA, 0);

    // branch s2: input projections (independent of adjacency)
    gemm_news0_kernel<<<(NN + 127) / 128, 256, GEMM_SMEM, s2>>>(x_news, nw_W, nw_b);
    comp0_kernel<<<(NC + 7) / 8, 256, 0, s2>>>(x_comp, cw_W, cw_b);
    cudaEventRecord(eB, s2);

    // cross-join: each branch needs the other's outputs
    cudaStreamWaitEvent(0, eB, 0);
    cudaStreamWaitEvent(s2, eA, 0);

    // ---- 3-chunk pipelined news gather + update ----
    const int NB = (NN + 127) / 128;       // 782 blocks
    const int B1 = 261, B2 = 261;          // chunk block counts
    const int R1 = B1 * 128;               // 33408
    const int R2 = R1 + B2 * 128;          // 66816

    // origin: g1 then nu chunks (nu2/nu3 gated by re-recorded events)
    gatherh_kernel<<<(R1 * 32 + 255) / 256, 256>>>(p_xn0h, p_bufS, p_cntS, p_aggNh, 0, R1, CAP_SIM);
    cudaEventRecord(eA, 0);  // reuse: g1 done

    // s2: g2, g3 immediately after g1 (overlapping nu1/nu2), then company chain
    cudaStreamWaitEvent(s2, eA, 0);
    gatherh_kernel<<<((R2 - R1) * 32 + 255) / 256, 256, 0, s2>>>(p_xn0h, p_bufS, p_cntS, p_aggNh, R1, R2, CAP_SIM);
    cudaEventRecord(eB, s2);  // reuse: g2 done
    gatherh_kernel<<<((NN - R2) * 32 + 255) / 256, 256, 0, s2>>>(p_xn0h, p_bufS, p_cntS, p_aggNh, R2, NN, CAP_SIM);
    cudaEventRecord(e0, s2);  // reuse: g3 done
    gatherh_kernel<<<(NC * 32 + 255) / 256, 256, 0, s2>>>(p_xn0h, p_bufM, p_cntM, p_aggCmh, 0, NC, CAP_MEN);
    gatherh_kernel<<<(NC * 32 + 255) / 256, 256, 0, s2>>>(p_xc0h, p_bufR, p_cntR, p_aggCrh, 0, NC, CAP_REL);
    comp1_kernel<<<(NC + 7) / 8, 256, 56000, s2>>>(c1_Wl, c1_bl, c1_Wr, n1c_g, n1c_b);
    gatherh_kernel<<<(NC * 32 + 255) / 256, 256, 0, s2>>>(p_xc1h, p_bufR, p_cntR, p_aggCrh, 0, NC, CAP_REL);
    cudaEventRecord(e3, s2);  // company chain done

    // origin: nu pipeline
    news_update_kernel<<<B1, 256, NU_SMEM>>>(c1_Wl, c1_bl, c1_Wr, n1n_g, n1n_b, 0);
    cudaStreamWaitEvent(0, eB, 0);
    news_update_kernel<<<B2, 256, NU_SMEM>>>(c1_Wl, c1_bl, c1_Wr, n1n_g, n1n_b, B1);
    cudaStreamWaitEvent(0, e0, 0);
    news_update_kernel<<<NB - B1 - B2, 256, NU_SMEM>>>(c1_Wl, c1_bl, c1_Wr, n1n_g, n1n_b, B1 + B2);

    // origin: layer-2 mentions gather (writes the SEPARATE aggCm2h — no WAR with comp1's read
    // of aggCmh on s2), then final kernel after s2's company chain completes.
    gatherh_kernel<<<(NC * 32 + 255) / 256, 256>>>(p_xn1h, p_bufM, p_cntM, p_aggCm2h, 0, NC, CAP_MEN);
    cudaStreamWaitEvent(0, e3, 0);
    compF_kernel<<<(NC + 7) / 8, 256, 66048>>>(c2_Wl, c2_bl, c2_Wr, cls_W1, cls_b1, cls_W2, cls_b2, out);
}

// round 14
// speedup vs baseline: 1.0467x; 1.0467x over previous
#include <cuda_runtime.h>
#include <cuda_fp16.h>
#include <mma.h>

using namespace nvcuda;

#define NN 100000
#define NC 5000
#define CAP_SIM 128
#define CAP_MEN 320
#define CAP_REL 128

// ---------------- scratch (device globals; no allocs allowed) ----------------
__device__ __half2 g_xn0h[NN * 32];
__device__ __half2 g_xn1h[NN * 32];
__device__ __half2 g_aggNh[NN * 32];
__device__ float g_xc0[NC * 64];
__device__ __half2 g_xc0h[NC * 32];
__device__ float g_xc1[NC * 64];
__device__ __half2 g_xc1h[NC * 32];
__device__ __half2 g_aggCmh[NC * 32];
__device__ __half2 g_aggCrh[NC * 32];
__device__ int g_bufS[NN * CAP_SIM];
__device__ int g_bufM[NC * CAP_MEN];
__device__ int g_bufR[NC * CAP_REL];
__device__ int g_cntS[NN];
__device__ int g_cntM[NC];
__device__ int g_cntR[NC];

__device__ __forceinline__ unsigned h2u(__half2 h) {
    return *reinterpret_cast<unsigned*>(&h);
}
__device__ __forceinline__ float2 uh2f2(unsigned u) {
    __half2 h = *reinterpret_cast<__half2*>(&u);
    return __half22float2(h);
}

// ---------------- zero adjacency counters ----------------
__global__ void zero_cnt_kernel() {
    int i = blockIdx.x * blockDim.x + threadIdx.x;
    if (i < NN) g_cntS[i] = 0;
    if (i < NC) { g_cntM[i] = 0; g_cntR[i] = 0; }
}

// ---------------- build capped-bucket CSR for all 3 relations ----------------
__global__ void fill_kernel(const int* __restrict__ es_src, const int* __restrict__ es_dst,
                            const int* __restrict__ mn_src, const int* __restrict__ mn_dst,
                            const int* __restrict__ rl_src, const int* __restrict__ rl_dst,
                            int Es, int Em, int Er) {
    int i = blockIdx.x * blockDim.x + threadIdx.x;
    if (i < Es) {
        int d = __ldg(es_dst + i);
        int p = atomicAdd(&g_cntS[d], 1);
        if (p < CAP_SIM) g_bufS[d * CAP_SIM + p] = __ldg(es_src + i);
    }
    if (i < Em) {
        int d = __ldg(mn_dst + i);
        int p = atomicAdd(&g_cntM[d], 1);
        if (p < CAP_MEN) g_bufM[d * CAP_MEN + p] = __ldg(mn_src + i);
    }
    if (i < Er) {
        int d = __ldg(rl_dst + i);
        int p = atomicAdd(&g_cntR[d], 1);
        if (p < CAP_REL) g_bufR[d * CAP_REL + p] = __ldg(rl_src + i);
    }
}

// ---------------- gather-mean fp16 -> fp16: warp per row, LDG.128 (4 rows / load) ----------------
// lane = off + 8*sub: lane loads the 16-byte chunk `off` of neighbor slot `sub`.
// Two independent quad-loads per iteration (8 neighbors) -> 512 B in flight per LDG slot.
__global__ void __launch_bounds__(256) gatherh_kernel(const __half2* __restrict__ xt,
                                                      const int* __restrict__ buf,
                                                      const int* __restrict__ cnt,
                                                      __half2* __restrict__ agg,
                                                      int nrows, int cap) {
    int gw = (blockIdx.x * 256 + threadIdx.x) >> 5;
    int lane = threadIdx.x & 31;
    if (gw >= nrows) return;
    int n = cnt[gw];
    if (n > cap) n = cap;
    const int* lst = buf + gw * cap;
    const uint4* xt4 = (const uint4*)xt;  // row = 8 x uint4 (128 B, aligned)
    const int sub = lane >> 3;
    const int off = lane & 7;

    float2 a0 = {0.f, 0.f}, a1 = {0.f, 0.f}, a2 = {0.f, 0.f}, a3 = {0.f, 0.f};
    float2 b0 = {0.f, 0.f}, b1 = {0.f, 0.f}, b2 = {0.f, 0.f}, b3 = {0.f, 0.f};

    int n8 = n >> 3;
    for (int i = 0; i < n8; i++) {
        int4 q0 = __ldg((const int4*)lst + 2 * i);
        int4 q1 = __ldg((const int4*)lst + 2 * i + 1);
        int s0 = (sub == 0) ? q0.x : (sub == 1) ? q0.y : (sub == 2) ? q0.z : q0.w;
        int s1 = (sub == 0) ? q1.x : (sub == 1) ? q1.y : (sub == 2) ? q1.z : q1.w;
        uint4 v0 = __ldg(xt4 + s0 * 8 + off);
        uint4 v1 = __ldg(xt4 + s1 * 8 + off);
        float2 f;
        f = uh2f2(v0.x); a0.x += f.x; a0.y += f.y;
        f = uh2f2(v0.y); a1.x += f.x; a1.y += f.y;
        f = uh2f2(v0.z); a2.x += f.x; a2.y += f.y;
        f = uh2f2(v0.w); a3.x += f.x; a3.y += f.y;
        f = uh2f2(v1.x); b0.x += f.x; b0.y += f.y;
        f = uh2f2(v1.y); b1.x += f.x; b1.y += f.y;
        f = uh2f2(v1.z); b2.x += f.x; b2.y += f.y;
        f = uh2f2(v1.w); b3.x += f.x; b3.y += f.y;
    }
    // tail: up to 7 neighbors, two predicated quad passes
    int base = n8 << 3;
#pragma unroll
    for (int t = 0; t < 2; t++) {
        int e = base + t * 4 + sub;
        if (e < n) {
            int s = __ldg(lst + e);
            uint4 v = __ldg(xt4 + s * 8 + off);
            float2 f;
            f = uh2f2(v.x); a0.x += f.x; a0.y += f.y;
            f = uh2f2(v.y); a1.x += f.x; a1.y += f.y;
            f = uh2f2(v.z); a2.x += f.x; a2.y += f.y;
            f = uh2f2(v.w); a3.x += f.x; a3.y += f.y;
        }
    }
    // fold the two ILP banks, then butterfly across the 4 sub-groups
    float r[8];
    r[0] = a0.x + b0.x; r[1] = a0.y + b0.y;
    r[2] = a1.x + b1.x; r[3] = a1.y + b1.y;
    r[4] = a2.x + b2.x; r[5] = a2.y + b2.y;
    r[6] = a3.x + b3.x; r[7] = a3.y + b3.y;
#pragma unroll
    for (int d = 8; d <= 16; d <<= 1) {
#pragma unroll
        for (int j = 0; j < 8; j++) r[j] += __shfl_xor_sync(0xffffffffu, r[j], d);
    }
    if (lane < 8) {
        float inv = 1.f / (float)(n < 1 ? 1 : n);
        uint4 h;
        h.x = h2u(__floats2half2_rn(r[0] * inv, r[1] * inv));
        h.y = h2u(__floats2half2_rn(r[2] * inv, r[3] * inv));
        h.z = h2u(__floats2half2_rn(r[4] * inv, r[5] * inv));
        h.w = h2u(__floats2half2_rn(r[6] * inv, r[7] * inv));
        ((uint4*)(agg + gw * 32))[off] = h;
    }
}

// ---------------- input GEMM (news): wmma tf32, 128x64 tile, 8 warps ----------------
__global__ void __launch_bounds__(256) gemm_news0_kernel(const float* __restrict__ X,
                                                         const float* __restrict__ W,
                                                         const float* __restrict__ b) {
    extern __shared__ float sm[];
    float* As = sm;            // 128 x 36 (stride-padded)
    float* Bs = sm + 4608;     // 32 x 68
    float* Cs = sm;            // 128 x 64 (reuse after mainloop)
    float* xs384 = sm + 8192;  // 128
    const int tid = threadIdx.x;
    const int wid = tid >> 5;
    const int row0 = blockIdx.x * 128;

    if (tid < 128) {
        int row = row0 + tid;
        xs384[tid] = (row < NN) ? __ldg(X + row * 385 + 384) : 0.f;
    }

    wmma::fragment<wmma::accumulator, 16, 16, 8, float> cfr[4];
#pragma unroll
    for (int c = 0; c < 4; c++) wmma::fill_fragment(cfr[c], 0.f);

    for (int kc = 0; kc < 384; kc += 32) {
#pragma unroll 4
        for (int idx = tid; idx < 4096; idx += 256) {
            int r = idx >> 5, k = idx & 31;
            int row = row0 + r;
            As[r * 36 + k] = (row < NN) ? X[row * 385 + kc + k] : 0.f;
        }
#pragma unroll 2
        for (int idx = tid; idx < 2048; idx += 256) {
            int k = idx >> 6, n = idx & 63;
            Bs[k * 68 + n] = W[(kc + k) * 64 + n];
        }
        __syncthreads();
#pragma unroll
        for (int k0 = 0; k0 < 32; k0 += 8) {
            wmma::fragment<wmma::matrix_a, 16, 16, 8, wmma::precision::tf32, wmma::row_major> af;
            wmma::load_matrix_sync(af, As + wid * 16 * 36 + k0, 36);
#pragma unroll
            for (int i = 0; i < af.num_elements; i++) af.x[i] = wmma::__float_to_tf32(af.x[i]);
#pragma unroll
            for (int c = 0; c < 4; c++) {
                wmma::fragment<wmma::matrix_b, 16, 16, 8, wmma::precision::tf32, wmma::row_major> bf;
                wmma::load_matrix_sync(bf, Bs + k0 * 68 + c * 16, 68);
#pragma unroll
                for (int i = 0; i < bf.num_elements; i++) bf.x[i] = wmma::__float_to_tf32(bf.x[i]);
                wmma::mma_sync(cfr[c], af, bf, cfr[c]);
            }
        }
        __syncthreads();
    }

#pragma unroll
    for (int c = 0; c < 4; c++)
        wmma::store_matrix_sync(Cs + wid * 16 * 64 + c * 16, cfr[c], 64, wmma::mem_row_major);
    __syncthreads();

    int r = tid >> 1, half = tid & 1;
    int row = row0 + r;
    if (row < NN) {
        float x384 = xs384[r];
        const float* w384 = W + 384 * 64 + half * 32;
        const float* crow = Cs + r * 64 + half * 32;
        const float* brow = b + half * 32;
        unsigned hv[16];
#pragma unroll
        for (int j = 0; j < 16; j++) {
            float v0 = fmaxf(crow[2 * j] + __ldg(brow + 2 * j) + x384 * __ldg(w384 + 2 * j), 0.f);
            float v1 = fmaxf(crow[2 * j + 1] + __ldg(brow + 2 * j + 1) + x384 * __ldg(w384 + 2 * j + 1), 0.f);
            hv[j] = h2u(__floats2half2_rn(v0, v1));
        }
        uint4* outh = (uint4*)(g_xn0h + row * 32 + half * 16);
#pragma unroll
        for (int q = 0; q < 4; q++)
            outh[q] = make_uint4(hv[4 * q], hv[4 * q + 1], hv[4 * q + 2], hv[4 * q + 3]);
    }
}

// ---------------- input GEMM (company): warp-per-row ----------------
__global__ void __launch_bounds__(256) comp0_kernel(const float* __restrict__ Xc,
                                                    const float* __restrict__ W,
                                                    const float* __restrict__ b) {
    __shared__ float ws[24 * 64];
    __shared__ float bs[64];
    __shared__ float xrow[8][24];
    int tid = threadIdx.x, lane = tid & 31, w = tid >> 5;
    for (int i = tid; i < 24 * 64; i += 256) ws[i] = W[i];
    if (tid < 64) bs[tid] = b[tid];
    int row = blockIdx.x * 8 + w;
    if (row < NC && lane < 24) xrow[w][lane] = Xc[row * 24 + lane];
    __syncthreads();
    if (row >= NC) return;
    float2 acc = make_float2(bs[2 * lane], bs[2 * lane + 1]);
#pragma unroll
    for (int k = 0; k < 24; k++) {
        float xv = xrow[w][k];
        float2 wv = ((const float2*)(ws + k * 64))[lane];
        acc.x += xv * wv.x;
        acc.y += xv * wv.y;
    }
    float2 o = make_float2(fmaxf(acc.x, 0.f), fmaxf(acc.y, 0.f));
    ((float2*)(g_xc0 + row * 64))[lane] = o;
    g_xc0h[row * 32 + lane] = __floats2half2_rn(o.x, o.y);
}

// ---------------- layer-1 news update: fp16 wmma dual-GEMM + LN, fp16 out ----------------
__global__ void __launch_bounds__(256) news_update_kernel(
    const float* __restrict__ Wl, const float* __restrict__ bl,
    const float* __restrict__ Wr, const float* __restrict__ gam,
    const float* __restrict__ bet) {
    extern __shared__ float smf[];
    __half* Asm = (__half*)smf;              // 128 x 72 (agg)
    __half* Bsm = Asm + 128 * 72;            // 128 x 72 (xn0)
    float* Cs = smf;                         // 128 x 64 fp32 (reuses A/B region)
    __half* Wlm = Bsm + 128 * 72;            // 64 x 72
    __half* Wrm = Wlm + 64 * 72;             // 64 x 72
    const int tid = threadIdx.x;
    const int wid = tid >> 5;
    const int row0 = blockIdx.x * 128;

#pragma unroll
    for (int idx = tid; idx < 1024; idx += 256) {
        int r = idx >> 3, q = idx & 7;
        int grow = row0 + r;
        uint4 va = make_uint4(0u, 0u, 0u, 0u), vb = va;
        if (grow < NN) {
            va = __ldg((const uint4*)(g_aggNh + grow * 32) + q);
            vb = __ldg((const uint4*)(g_xn0h + grow * 32) + q);
        }
        *(uint4*)(Asm + r * 72 + q * 8) = va;
        *(uint4*)(Bsm + r * 72 + q * 8) = vb;
    }
#pragma unroll
    for (int idx = tid; idx < 4096; idx += 256) {
        int k = idx >> 6, n = idx & 63;
        Wlm[k * 72 + n] = __float2half(Wl[idx]);
        Wrm[k * 72 + n] = __float2half(Wr[idx]);
    }
    __syncthreads();

    wmma::fragment<wmma::accumulator, 16, 16, 16, float> cfr[4];
#pragma unroll
    for (int c = 0; c < 4; c++) wmma::fill_fragment(cfr[c], 0.f);

#pragma unroll
    for (int k0 = 0; k0 < 64; k0 += 16) {
        wmma::fragment<wmma::matrix_a, 16, 16, 16, __half, wmma::row_major> afA, afB;
        wmma::load_matrix_sync(afA, Asm + wid * 16 * 72 + k0, 72);
        wmma::load_matrix_sync(afB, Bsm + wid * 16 * 72 + k0, 72);
#pragma unroll
        for (int c = 0; c < 4; c++) {
            wmma::fragment<wmma::matrix_b, 16, 16, 16, __half, wmma::row_major> bfL, bfR;
            wmma::load_matrix_sync(bfL, Wlm + k0 * 72 + c * 16, 72);
            wmma::load_matrix_sync(bfR, Wrm + k0 * 72 + c * 16, 72);
            wmma::mma_sync(cfr[c], afA, bfL, cfr[c]);
            wmma::mma_sync(cfr[c], afB, bfR, cfr[c]);
        }
    }
    __syncthreads();
#pragma unroll
    for (int c = 0; c < 4; c++)
        wmma::store_matrix_sync(Cs + wid * 16 * 64 + c * 16, cfr[c], 64, wmma::mem_row_major);
    __syncthreads();

    int r = tid >> 1, half = tid & 1;
    int row = row0 + r;
    float v[32];
    const float* crow = Cs + r * 64 + half * 32;
    const float* blh = bl + half * 32;
    float ssum = 0.f;
#pragma unroll
    for (int j = 0; j < 32; j++) {
        v[j] = fmaxf(crow[j] + __ldg(blh + j), 0.f);
        ssum += v[j];
    }
    ssum += __shfl_xor_sync(0xffffffffu, ssum, 1);
    float m = ssum * (1.f / 64.f);
    float var = 0.f;
#pragma unroll
    for (int j = 0; j < 32; j++) { float d = v[j] - m; var += d * d; }
    var += __shfl_xor_sync(0xffffffffu, var, 1);
    float s = rsqrtf(var * (1.f / 64.f) + 1e-5f);
    if (row < NN) {
        const float* gmh = gam + half * 32;
        const float* bth = bet + half * 32;
        unsigned hv[16];
#pragma unroll
        for (int j = 0; j < 16; j++) {
            float o0 = (v[2 * j] - m) * s * __ldg(gmh + 2 * j) + __ldg(bth + 2 * j);
            float o1 = (v[2 * j + 1] - m) * s * __ldg(gmh + 2 * j + 1) + __ldg(bth + 2 * j + 1);
            hv[j] = h2u(__floats2half2_rn(o0, o1));
        }
        uint4* outh = (uint4*)(g_xn1h + row * 32 + half * 16);
#pragma unroll
        for (int q = 0; q < 4; q++)
            outh[q] = make_uint4(hv[4 * q], hv[4 * q + 1], hv[4 * q + 2], hv[4 * q + 3]);
    }
}

// ---------------- layer-1 company update: warp-per-row ----------------
__global__ void __launch_bounds__(256) comp1_kernel(const float* __restrict__ Wl,
                                                    const float* __restrict__ bl,
                                                    const float* __restrict__ Wr,
                                                    const float* __restrict__ gam,
                                                    const float* __restrict__ bet) {
    extern __shared__ float sm[];
    float* wl1 = sm;            // 4096
    float* wl2 = sm + 4096;     // 4096
    float* wrs = sm + 8192;     // 4096 = Wr1 + Wr2
    float* bsum = sm + 12288;   // 64
    float* stg = sm + 12352;    // 8 warps * 192
    int tid = threadIdx.x, lane = tid & 31, w = tid >> 5;
    for (int i = tid; i < 4096; i += 256) {
        wl1[i] = Wl[4096 + i];
        wl2[i] = Wl[8192 + i];
        wrs[i] = Wr[4096 + i] + Wr[8192 + i];
    }
    if (tid < 64) bsum[tid] = bl[64 + tid] + bl[128 + tid];
    int row = blockIdx.x * 8 + w;
    float* S = stg + w * 192;
    if (row < NC) {
        ((float2*)S)[lane] = __half22float2(__ldg(g_aggCmh + row * 32 + lane));
        ((float2*)(S + 64))[lane] = __half22float2(__ldg(g_aggCrh + row * 32 + lane));
        ((float2*)(S + 128))[lane] = ((const float2*)(g_xc0 + row * 64))[lane];
    }
    __syncthreads();
    if (row >= NC) return;
    float2 acc = make_float2(bsum[2 * lane], bsum[2 * lane + 1]);
#pragma unroll 8
    for (int k = 0; k < 64; k++) {
        float am = S[k], ar = S[64 + k], xk = S[128 + k];
        float2 w1 = ((const float2*)(wl1 + k * 64))[lane];
        float2 w2 = ((const float2*)(wl2 + k * 64))[lane];
        float2 w3 = ((const float2*)(wrs + k * 64))[lane];
        acc.x += am * w1.x + ar * w2.x + xk * w3.x;
        acc.y += am * w1.y + ar * w2.y + xk * w3.y;
    }
    float v0 = fmaxf(acc.x + S[128 + 2 * lane], 0.f);
    float v1 = fmaxf(acc.y + S[128 + 2 * lane + 1], 0.f);
    float ssum = v0 + v1;
#pragma unroll
    for (int o = 16; o > 0; o >>= 1) ssum += __shfl_xor_sync(0xffffffffu, ssum, o);
    float m = ssum * (1.f / 64.f);
    float d0 = v0 - m, d1 = v1 - m;
    float vs = d0 * d0 + d1 * d1;
#pragma unroll
    for (int o = 16; o > 0; o >>= 1) vs += __shfl_xor_sync(0xffffffffu, vs, o);
    float s = rsqrtf(vs * (1.f / 64.f) + 1e-5f);
    float2 o2;
    o2.x = d0 * s * __ldg(gam + 2 * lane) + __ldg(bet + 2 * lane);
    o2.y = d1 * s * __ldg(gam + 2 * lane + 1) + __ldg(bet + 2 * lane + 1);
    ((float2*)(g_xc1 + row * 64))[lane] = o2;
    g_xc1h[row * 32 + lane] = __floats2half2_rn(o2.x, o2.y);
}

// ---------------- layer-2 company + classifier: warp-per-row (on2 dead in reference) ----------------
__global__ void __launch_bounds__(256) compF_kernel(const float* __restrict__ Wl,
                                                    const float* __restrict__ bl,
                                                    const float* __restrict__ Wr,
                                                    const float* __restrict__ W1,
                                                    const float* __restrict__ b1,
                                                    const float* __restrict__ W2,
                                                    const float* __restrict__ b2,
                                                    float* __restrict__ out) {
    extern __shared__ float sm[];
    float* wl1 = sm;             // 4096
    float* wl2 = sm + 4096;      // 4096
    float* wrs = sm + 8192;      // 4096
    float* bsum = sm + 12288;    // 64
    float* w1s = sm + 12352;     // 2048
    float* b1s = sm + 14400;     // 32
    float* w2s = sm + 14432;     // 32
    float* stg = sm + 14464;     // 8 * 192
    float* cst = sm + 14464 + 1536;  // 8 * 64
    int tid = threadIdx.x, lane = tid & 31, w = tid >> 5;
    for (int i = tid; i < 4096; i += 256) {
        wl1[i] = Wl[4096 + i];
        wl2[i] = Wl[8192 + i];
        wrs[i] = Wr[4096 + i] + Wr[8192 + i];
    }
    for (int i = tid; i < 2048; i += 256) w1s[i] = W1[i];
    if (tid < 64) bsum[tid] = bl[64 + tid] + bl[128 + tid];
    if (tid < 32) { b1s[tid] = b1[tid]; w2s[tid] = W2[tid]; }
    int row = blockIdx.x * 8 + w;
    float* S = stg + w * 192;
    if (row < NC) {
        ((float2*)S)[lane] = __half22float2(__ldg(g_aggCmh + row * 32 + lane));
        ((float2*)(S + 64))[lane] = __half22float2(__ldg(g_aggCrh + row * 32 + lane));
        ((float2*)(S + 128))[lane] = ((const float2*)(g_xc1 + row * 64))[lane];
    }
    __syncthreads();
    if (row >= NC) return;
    float2 acc = make_float2(bsum[2 * lane], bsum[2 * lane + 1]);
#pragma unroll 8
    for (int k = 0; k < 64; k++) {
        float am = S[k], ar = S[64 + k], xk = S[128 + k];
        float2 w1 = ((const float2*)(wl1 + k * 64))[lane];
        float2 w2 = ((const float2*)(wl2 + k * 64))[lane];
        float2 w3 = ((const float2*)(wrs + k * 64))[lane];
        acc.x += am * w1.x + ar * w2.x + xk * w3.x;
        acc.y += am * w1.y + ar * w2.y + xk * w3.y;
    }
    float* C = cst + w * 64;
    C[2 * lane] = fmaxf(acc.x + S[128 + 2 * lane], 0.f);
    C[2 * lane + 1] = fmaxf(acc.y + S[128 + 2 * lane + 1], 0.f);
    __syncwarp();
    float h = b1s[lane];
#pragma unroll 8
    for (int j = 0; j < 64; j++) h += C[j] * w1s[j * 32 + lane];
    float o = fmaxf(h, 0.f) * w2s[lane];
#pragma unroll
    for (int off = 16; off > 0; off >>= 1) o += __shfl_xor_sync(0xffffffffu, o, off);
    if (lane == 0) out[row] = o + __ldg(b2);
}

// ---------------- host launch (R8 schedule, verbatim) ----------------
extern "C" void kernel_launch(void* const* d_in, const int* in_sizes, int n_in,
                              void* d_out, int out_size) {
    const float* x_news  = (const float*)d_in[0];
    const float* x_comp  = (const float*)d_in[1];
    const int*   e_sim   = (const int*)d_in[2];
    const int*   men_src = (const int*)d_in[3];
    const int*   men_dst = (const int*)d_in[4];
    const int*   e_rel   = (const int*)d_in[5];
    const float* nw_W = (const float*)d_in[6];
    const float* nw_b = (const float*)d_in[7];
    const float* cw_W = (const float*)d_in[8];
    const float* cw_b = (const float*)d_in[9];
    const float* n1n_g = (const float*)d_in[10];
    const float* n1n_b = (const float*)d_in[11];
    const float* n1c_g = (const float*)d_in[12];
    const float* n1c_b = (const float*)d_in[13];
    const float* c1_Wl = (const float*)d_in[14];
    const float* c1_bl = (const float*)d_in[15];
    const float* c1_Wr = (const float*)d_in[16];
    const float* c2_Wl = (const float*)d_in[17];
    const float* c2_bl = (const float*)d_in[18];
    const float* c2_Wr = (const float*)d_in[19];
    const float* cls_W1 = (const float*)d_in[20];
    const float* cls_b1 = (const float*)d_in[21];
    const float* cls_W2 = (const float*)d_in[22];
    const float* cls_b2 = (const float*)d_in[23];
    float* out = (float*)d_out;

    const int Es = in_sizes[2] / 2;
    const int Em = in_sizes[3];
    const int Er = in_sizes[5] / 2;
    const int* es_src = e_sim;
    const int* es_dst = e_sim + Es;
    const int* rl_src = e_rel;
    const int* rl_dst = e_rel + Er;

    __half2 *p_xn0h, *p_xn1h, *p_xc0h, *p_xc1h, *p_aggNh, *p_aggCmh, *p_aggCrh;
    int *p_bufS, *p_bufM, *p_bufR, *p_cntS, *p_cntM, *p_cntR;
    cudaGetSymbolAddress((void**)&p_xn0h, g_xn0h);
    cudaGetSymbolAddress((void**)&p_xn1h, g_xn1h);
    cudaGetSymbolAddress((void**)&p_xc0h, g_xc0h);
    cudaGetSymbolAddress((void**)&p_xc1h, g_xc1h);
    cudaGetSymbolAddress((void**)&p_aggNh, g_aggNh);
    cudaGetSymbolAddress((void**)&p_aggCmh, g_aggCmh);
    cudaGetSymbolAddress((void**)&p_aggCrh, g_aggCrh);
    cudaGetSymbolAddress((void**)&p_bufS, g_bufS);
    cudaGetSymbolAddress((void**)&p_bufM, g_bufM);
    cudaGetSymbolAddress((void**)&p_bufR, g_bufR);
    cudaGetSymbolAddress((void**)&p_cntS, g_cntS);
    cudaGetSymbolAddress((void**)&p_cntM, g_cntM);
    cudaGetSymbolAddress((void**)&p_cntR, g_cntR);

    const int GEMM_SMEM = (8192 + 128) * 4;                       // 33280
    const int NU_SMEM = 2 * 128 * 72 * 2 + 2 * 64 * 72 * 2;       // 55296
    cudaFuncSetAttribute(news_update_kernel, cudaFuncAttributeMaxDynamicSharedMemorySize, NU_SMEM);
    cudaFuncSetAttribute(comp1_kernel, cudaFuncAttributeMaxDynamicSharedMemorySize, 56000);
    cudaFuncSetAttribute(compF_kernel, cudaFuncAttributeMaxDynamicSharedMemorySize, 66048);

    // ONE extra stream + 4 events (the budget proven to pass the teardown check)
    cudaStream_t s2;
    cudaStreamCreateWithFlags(&s2, cudaStreamNonBlocking);
    cudaEvent_t e0, eA, eB, e3;
    cudaEventCreateWithFlags(&e0, cudaEventDisableTiming);
    cudaEventCreateWithFlags(&eA, cudaEventDisableTiming);
    cudaEventCreateWithFlags(&eB, cudaEventDisableTiming);
    cudaEventCreateWithFlags(&e3, cudaEventDisableTiming);

    // fork s2 from the capture origin stream
    cudaEventRecord(e0, 0);
    cudaStreamWaitEvent(s2, e0, 0);

    // branch 0 (origin): adjacency build
    zero_cnt_kernel<<<(NN + 255) / 256, 256>>>();
    fill_kernel<<<(Es + 255) / 256, 256>>>(es_src, es_dst, men_src, men_dst,
                                           rl_src, rl_dst, Es, Em, Er);
    cudaEventRecord(eA, 0);

    // branch s2: input projections (independent of adjacency)
    gemm_news0_kernel<<<(NN + 127) / 128, 256, GEMM_SMEM, s2>>>(x_news, nw_W, nw_b);
    comp0_kernel<<<(NC + 7) / 8, 256, 0, s2>>>(x_comp, cw_W, cw_b);
    cudaEventRecord(eB, s2);

    // cross-join: each branch needs the other's outputs
    cudaStreamWaitEvent(0, eB, 0);
    cudaStreamWaitEvent(s2, eA, 0);

    // branch 0: big news gather + news update
    gatherh_kernel<<<(NN * 32 + 255) / 256, 256>>>(p_xn0h, p_bufS, p_cntS, p_aggNh, NN, CAP_SIM);
    news_update_kernel<<<(NN + 127) / 128, 256, NU_SMEM>>>(c1_Wl, c1_bl, c1_Wr, n1n_g, n1n_b);

    // branch s2: company gathers + company update + layer-2 rel gather (overlaps news_update)
    gatherh_kernel<<<(NC * 32 + 255) / 256, 256, 0, s2>>>(p_xn0h, p_bufM, p_cntM, p_aggCmh, NC, CAP_MEN);
    gatherh_kernel<<<(NC * 32 + 255) / 256, 256, 0, s2>>>(p_xc0h, p_bufR, p_cntR, p_aggCrh, NC, CAP_REL);
    comp1_kernel<<<(NC + 7) / 8, 256, 56000, s2>>>(c1_Wl, c1_bl, c1_Wr, n1c_g, n1c_b);
    gatherh_kernel<<<(NC * 32 + 255) / 256, 256, 0, s2>>>(p_xc1h, p_bufR, p_cntR, p_aggCrh, NC, CAP_REL);
    cudaEventRecord(e3, s2);

    // join and finish on origin stream
    cudaStreamWaitEvent(0, e3, 0);
    gatherh_kernel<<<(NC * 32 + 255) / 256, 256>>>(p_xn1h, p_bufM, p_cntM, p_aggCmh, NC, CAP_MEN);
    compF_kernel<<<(NC + 7) / 8, 256, 66048>>>(c2_Wl, c2_bl, c2_Wr, cls_W1, cls_b1, cls_W2, cls_b2, out);
}

// round 15
// speedup vs baseline: 1.0798x; 1.0316x over previous
#include <cuda_runtime.h>
#include <cuda_fp16.h>
#include <mma.h>

using namespace nvcuda;

#define NN 100000
#define NC 5000
#define CAP_SIM 128
#define CAP_MEN 320
#define CAP_REL 128

// ---------------- scratch (device globals; no allocs allowed) ----------------
__device__ __half2 g_xn0h[NN * 32];
__device__ __half2 g_xn1h[NN * 32];
__device__ __half2 g_aggNh[NN * 32];
__device__ float g_xc0[NC * 64];
__device__ __half2 g_xc0h[NC * 32];
__device__ float g_xc1[NC * 64];
__device__ __half2 g_xc1h[NC * 32];
__device__ __half2 g_aggCmh[NC * 32];
__device__ __half2 g_aggCm2h[NC * 32];   // layer-2 mentions mean (separate buffer: no WAR vs comp1)
__device__ __half2 g_aggCrh[NC * 32];
__device__ int g_bufS[NN * CAP_SIM];
__device__ int g_bufM[NC * CAP_MEN];
__device__ int g_bufR[NC * CAP_REL];
__device__ int g_cntS[NN];
__device__ int g_cntM[NC];
__device__ int g_cntR[NC];

__device__ __forceinline__ unsigned h2u(__half2 h) {
    return *reinterpret_cast<unsigned*>(&h);
}

// ---------------- zero adjacency counters ----------------
__global__ void zero_cnt_kernel() {
    int i = blockIdx.x * blockDim.x + threadIdx.x;
    if (i < NN) g_cntS[i] = 0;
    if (i < NC) { g_cntM[i] = 0; g_cntR[i] = 0; }
}

// ---------------- build capped-bucket CSR for all 3 relations ----------------
__global__ void fill_kernel(const int* __restrict__ es_src, const int* __restrict__ es_dst,
                            const int* __restrict__ mn_src, const int* __restrict__ mn_dst,
                            const int* __restrict__ rl_src, const int* __restrict__ rl_dst,
                            int Es, int Em, int Er) {
    int i = blockIdx.x * blockDim.x + threadIdx.x;
    if (i < Es) {
        int d = __ldg(es_dst + i);
        int p = atomicAdd(&g_cntS[d], 1);
        if (p < CAP_SIM) g_bufS[d * CAP_SIM + p] = __ldg(es_src + i);
    }
    if (i < Em) {
        int d = __ldg(mn_dst + i);
        int p = atomicAdd(&g_cntM[d], 1);
        if (p < CAP_MEN) g_bufM[d * CAP_MEN + p] = __ldg(mn_src + i);
    }
    if (i < Er) {
        int d = __ldg(rl_dst + i);
        int p = atomicAdd(&g_cntR[d], 1);
        if (p < CAP_REL) g_bufR[d * CAP_REL + p] = __ldg(rl_src + i);
    }
}

// ---------------- gather-mean fp16 -> fp16: warp per destination row (R8 verbatim) ----------------
__global__ void __launch_bounds__(256) gatherh_kernel(const __half2* __restrict__ xt,
                                                      const int* __restrict__ buf,
                                                      const int* __restrict__ cnt,
                                                      __half2* __restrict__ agg,
                                                      int nrows, int cap) {
    int gw = (blockIdx.x * 256 + threadIdx.x) >> 5;
    int lane = threadIdx.x & 31;
    if (gw >= nrows) return;
    int n = cnt[gw];
    if (n > cap) n = cap;
    const int* lst = buf + gw * cap;
    float2 a0 = {0.f, 0.f}, a1 = {0.f, 0.f}, a2 = {0.f, 0.f}, a3 = {0.f, 0.f};
    int n4 = n >> 2;
    for (int i = 0; i < n4; i++) {
        int4 s = __ldg((const int4*)lst + i);
        float2 v0 = __half22float2(__ldg(xt + s.x * 32 + lane));
        float2 v1 = __half22float2(__ldg(xt + s.y * 32 + lane));
        float2 v2 = __half22float2(__ldg(xt + s.z * 32 + lane));
        float2 v3 = __half22float2(__ldg(xt + s.w * 32 + lane));
        a0.x += v0.x; a0.y += v0.y;
        a1.x += v1.x; a1.y += v1.y;
        a2.x += v2.x; a2.y += v2.y;
        a3.x += v3.x; a3.y += v3.y;
    }
    for (int e = n4 << 2; e < n; e++) {
        int s = __ldg(lst + e);
        float2 v = __half22float2(__ldg(xt + s * 32 + lane));
        a0.x += v.x; a0.y += v.y;
    }
    float inv = 1.f / (float)(n < 1 ? 1 : n);
    agg[gw * 32 + lane] = __floats2half2_rn((a0.x + a1.x + a2.x + a3.x) * inv,
                                            (a0.y + a1.y + a2.y + a3.y) * inv);
}

// ---------------- input GEMM (news): wmma tf32, 128x64 tile, 8 warps ----------------
__global__ void __launch_bounds__(256) gemm_news0_kernel(const float* __restrict__ X,
                                                         const float* __restrict__ W,
                                                         const float* __restrict__ b) {
    extern __shared__ float sm[];
    float* As = sm;            // 128 x 36 (stride-padded)
    float* Bs = sm + 4608;     // 32 x 68
    float* Cs = sm;            // 128 x 64 (reuse after mainloop)
    float* xs384 = sm + 8192;  // 128
    const int tid = threadIdx.x;
    const int wid = tid >> 5;
    const int row0 = blockIdx.x * 128;

    if (tid < 128) {
        int row = row0 + tid;
        xs384[tid] = (row < NN) ? __ldg(X + row * 385 + 384) : 0.f;
    }

    wmma::fragment<wmma::accumulator, 16, 16, 8, float> cfr[4];
#pragma unroll
    for (int c = 0; c < 4; c++) wmma::fill_fragment(cfr[c], 0.f);

    for (int kc = 0; kc < 384; kc += 32) {
#pragma unroll 4
        for (int idx = tid; idx < 4096; idx += 256) {
            int r = idx >> 5, k = idx & 31;
            int row = row0 + r;
            As[r * 36 + k] = (row < NN) ? X[row * 385 + kc + k] : 0.f;
        }
#pragma unroll 2
        for (int idx = tid; idx < 2048; idx += 256) {
            int k = idx >> 6, n = idx & 63;
            Bs[k * 68 + n] = W[(kc + k) * 64 + n];
        }
        __syncthreads();
#pragma unroll
        for (int k0 = 0; k0 < 32; k0 += 8) {
            wmma::fragment<wmma::matrix_a, 16, 16, 8, wmma::precision::tf32, wmma::row_major> af;
            wmma::load_matrix_sync(af, As + wid * 16 * 36 + k0, 36);
#pragma unroll
            for (int i = 0; i < af.num_elements; i++) af.x[i] = wmma::__float_to_tf32(af.x[i]);
#pragma unroll
            for (int c = 0; c < 4; c++) {
                wmma::fragment<wmma::matrix_b, 16, 16, 8, wmma::precision::tf32, wmma::row_major> bf;
                wmma::load_matrix_sync(bf, Bs + k0 * 68 + c * 16, 68);
#pragma unroll
                for (int i = 0; i < bf.num_elements; i++) bf.x[i] = wmma::__float_to_tf32(bf.x[i]);
                wmma::mma_sync(cfr[c], af, bf, cfr[c]);
            }
        }
        __syncthreads();
    }

#pragma unroll
    for (int c = 0; c < 4; c++)
        wmma::store_matrix_sync(Cs + wid * 16 * 64 + c * 16, cfr[c], 64, wmma::mem_row_major);
    __syncthreads();

    int r = tid >> 1, half = tid & 1;
    int row = row0 + r;
    if (row < NN) {
        float x384 = xs384[r];
        const float* w384 = W + 384 * 64 + half * 32;
        const float* crow = Cs + r * 64 + half * 32;
        const float* brow = b + half * 32;
        unsigned hv[16];
#pragma unroll
        for (int j = 0; j < 16; j++) {
            float v0 = fmaxf(crow[2 * j] + __ldg(brow + 2 * j) + x384 * __ldg(w384 + 2 * j), 0.f);
            float v1 = fmaxf(crow[2 * j + 1] + __ldg(brow + 2 * j + 1) + x384 * __ldg(w384 + 2 * j + 1), 0.f);
            hv[j] = h2u(__floats2half2_rn(v0, v1));
        }
        uint4* outh = (uint4*)(g_xn0h + row * 32 + half * 16);
#pragma unroll
        for (int q = 0; q < 4; q++)
            outh[q] = make_uint4(hv[4 * q], hv[4 * q + 1], hv[4 * q + 2], hv[4 * q + 3]);
    }
}

// ---------------- input GEMM (company): warp-per-row ----------------
__global__ void __launch_bounds__(256) comp0_kernel(const float* __restrict__ Xc,
                                                    const float* __restrict__ W,
                                                    const float* __restrict__ b) {
    __shared__ float ws[24 * 64];
    __shared__ float bs[64];
    __shared__ float xrow[8][24];
    int tid = threadIdx.x, lane = tid & 31, w = tid >> 5;
    for (int i = tid; i < 24 * 64; i += 256) ws[i] = W[i];
    if (tid < 64) bs[tid] = b[tid];
    int row = blockIdx.x * 8 + w;
    if (row < NC && lane < 24) xrow[w][lane] = Xc[row * 24 + lane];
    __syncthreads();
    if (row >= NC) return;
    float2 acc = make_float2(bs[2 * lane], bs[2 * lane + 1]);
#pragma unroll
    for (int k = 0; k < 24; k++) {
        float xv = xrow[w][k];
        float2 wv = ((const float2*)(ws + k * 64))[lane];
        acc.x += xv * wv.x;
        acc.y += xv * wv.y;
    }
    float2 o = make_float2(fmaxf(acc.x, 0.f), fmaxf(acc.y, 0.f));
    ((float2*)(g_xc0 + row * 64))[lane] = o;
    g_xc0h[row * 32 + lane] = __floats2half2_rn(o.x, o.y);
}

// ---------------- layer-1 news update: fp16 wmma dual-GEMM + LN, fp16 out ----------------
__global__ void __launch_bounds__(256) news_update_kernel(
    const float* __restrict__ Wl, const float* __restrict__ bl,
    const float* __restrict__ Wr, const float* __restrict__ gam,
    const float* __restrict__ bet) {
    extern __shared__ float smf[];
    __half* Asm = (__half*)smf;              // 128 x 72 (agg)
    __half* Bsm = Asm + 128 * 72;            // 128 x 72 (xn0)
    float* Cs = smf;                         // 128 x 64 fp32 (reuses A/B region)
    __half* Wlm = Bsm + 128 * 72;            // 64 x 72
    __half* Wrm = Wlm + 64 * 72;             // 64 x 72
    const int tid = threadIdx.x;
    const int wid = tid >> 5;
    const int row0 = blockIdx.x * 128;

#pragma unroll
    for (int idx = tid; idx < 1024; idx += 256) {
        int r = idx >> 3, q = idx & 7;
        int grow = row0 + r;
        uint4 va = make_uint4(0u, 0u, 0u, 0u), vb = va;
        if (grow < NN) {
            va = __ldg((const uint4*)(g_aggNh + grow * 32) + q);
            vb = __ldg((const uint4*)(g_xn0h + grow * 32) + q);
        }
        *(uint4*)(Asm + r * 72 + q * 8) = va;
        *(uint4*)(Bsm + r * 72 + q * 8) = vb;
    }
#pragma unroll
    for (int idx = tid; idx < 4096; idx += 256) {
        int k = idx >> 6, n = idx & 63;
        Wlm[k * 72 + n] = __float2half(Wl[idx]);
        Wrm[k * 72 + n] = __float2half(Wr[idx]);
    }
    __syncthreads();

    wmma::fragment<wmma::accumulator, 16, 16, 16, float> cfr[4];
#pragma unroll
    for (int c = 0; c < 4; c++) wmma::fill_fragment(cfr[c], 0.f);

#pragma unroll
    for (int k0 = 0; k0 < 64; k0 += 16) {
        wmma::fragment<wmma::matrix_a, 16, 16, 16, __half, wmma::row_major> afA, afB;
        wmma::load_matrix_sync(afA, Asm + wid * 16 * 72 + k0, 72);
        wmma::load_matrix_sync(afB, Bsm + wid * 16 * 72 + k0, 72);
#pragma unroll
        for (int c = 0; c < 4; c++) {
            wmma::fragment<wmma::matrix_b, 16, 16, 16, __half, wmma::row_major> bfL, bfR;
            wmma::load_matrix_sync(bfL, Wlm + k0 * 72 + c * 16, 72);
            wmma::load_matrix_sync(bfR, Wrm + k0 * 72 + c * 16, 72);
            wmma::mma_sync(cfr[c], afA, bfL, cfr[c]);
            wmma::mma_sync(cfr[c], afB, bfR, cfr[c]);
        }
    }
    __syncthreads();
#pragma unroll
    for (int c = 0; c < 4; c++)
        wmma::store_matrix_sync(Cs + wid * 16 * 64 + c * 16, cfr[c], 64, wmma::mem_row_major);
    __syncthreads();

    int r = tid >> 1, half = tid & 1;
    int row = row0 + r;
    float v[32];
    const float* crow = Cs + r * 64 + half * 32;
    const float* blh = bl + half * 32;
    float ssum = 0.f;
#pragma unroll
    for (int j = 0; j < 32; j++) {
        v[j] = fmaxf(crow[j] + __ldg(blh + j), 0.f);
        ssum += v[j];
    }
    ssum += __shfl_xor_sync(0xffffffffu, ssum, 1);
    float m = ssum * (1.f / 64.f);
    float var = 0.f;
#pragma unroll
    for (int j = 0; j < 32; j++) { float d = v[j] - m; var += d * d; }
    var += __shfl_xor_sync(0xffffffffu, var, 1);
    float s = rsqrtf(var * (1.f / 64.f) + 1e-5f);
    if (row < NN) {
        const float* gmh = gam + half * 32;
        const float* bth = bet + half * 32;
        unsigned hv[16];
#pragma unroll
        for (int j = 0; j < 16; j++) {
            float o0 = (v[2 * j] - m) * s * __ldg(gmh + 2 * j) + __ldg(bth + 2 * j);
            float o1 = (v[2 * j + 1] - m) * s * __ldg(gmh + 2 * j + 1) + __ldg(bth + 2 * j + 1);
            hv[j] = h2u(__floats2half2_rn(o0, o1));
        }
        uint4* outh = (uint4*)(g_xn1h + row * 32 + half * 16);
#pragma unroll
        for (int q = 0; q < 4; q++)
            outh[q] = make_uint4(hv[4 * q], hv[4 * q + 1], hv[4 * q + 2], hv[4 * q + 3]);
    }
}

// ---------------- layer-1 company update: warp-per-row ----------------
__global__ void __launch_bounds__(256) comp1_kernel(const float* __restrict__ Wl,
                                                    const float* __restrict__ bl,
                                                    const float* __restrict__ Wr,
                                                    const float* __restrict__ gam,
                                                    const float* __restrict__ bet) {
    extern __shared__ float sm[];
    float* wl1 = sm;            // 4096
    float* wl2 = sm + 4096;     // 4096
    float* wrs = sm + 8192;     // 4096 = Wr1 + Wr2
    float* bsum = sm + 12288;   // 64
    float* stg = sm + 12352;    // 8 warps * 192
    int tid = threadIdx.x, lane = tid & 31, w = tid >> 5;
    for (int i = tid; i < 4096; i += 256) {
        wl1[i] = Wl[4096 + i];
        wl2[i] = Wl[8192 + i];
        wrs[i] = Wr[4096 + i] + Wr[8192 + i];
    }
    if (tid < 64) bsum[tid] = bl[64 + tid] + bl[128 + tid];
    int row = blockIdx.x * 8 + w;
    float* S = stg + w * 192;
    if (row < NC) {
        ((float2*)S)[lane] = __half22float2(__ldg(g_aggCmh + row * 32 + lane));
        ((float2*)(S + 64))[lane] = __half22float2(__ldg(g_aggCrh + row * 32 + lane));
        ((float2*)(S + 128))[lane] = ((const float2*)(g_xc0 + row * 64))[lane];
    }
    __syncthreads();
    if (row >= NC) return;
    float2 acc = make_float2(bsum[2 * lane], bsum[2 * lane + 1]);
#pragma unroll 8
    for (int k = 0; k < 64; k++) {
        float am = S[k], ar = S[64 + k], xk = S[128 + k];
        float2 w1 = ((const float2*)(wl1 + k * 64))[lane];
        float2 w2 = ((const float2*)(wl2 + k * 64))[lane];
        float2 w3 = ((const float2*)(wrs + k * 64))[lane];
        acc.x += am * w1.x + ar * w2.x + xk * w3.x;
        acc.y += am * w1.y + ar * w2.y + xk * w3.y;
    }
    float v0 = fmaxf(acc.x + S[128 + 2 * lane], 0.f);
    float v1 = fmaxf(acc.y + S[128 + 2 * lane + 1], 0.f);
    float ssum = v0 + v1;
#pragma unroll
    for (int o = 16; o > 0; o >>= 1) ssum += __shfl_xor_sync(0xffffffffu, ssum, o);
    float m = ssum * (1.f / 64.f);
    float d0 = v0 - m, d1 = v1 - m;
    float vs = d0 * d0 + d1 * d1;
#pragma unroll
    for (int o = 16; o > 0; o >>= 1) vs += __shfl_xor_sync(0xffffffffu, vs, o);
    float s = rsqrtf(vs * (1.f / 64.f) + 1e-5f);
    float2 o2;
    o2.x = d0 * s * __ldg(gam + 2 * lane) + __ldg(bet + 2 * lane);
    o2.y = d1 * s * __ldg(gam + 2 * lane + 1) + __ldg(bet + 2 * lane + 1);
    ((float2*)(g_xc1 + row * 64))[lane] = o2;
    g_xc1h[row * 32 + lane] = __floats2half2_rn(o2.x, o2.y);
}

// ---------------- layer-2 company + classifier: warp-per-row (on2 dead in reference) ----------------
__global__ void __launch_bounds__(256) compF_kernel(const float* __restrict__ Wl,
                                                    const float* __restrict__ bl,
                                                    const float* __restrict__ Wr,
                                                    const float* __restrict__ W1,
                                                    const float* __restrict__ b1,
                                                    const float* __restrict__ W2,
                                                    const float* __restrict__ b2,
                                                    float* __restrict__ out) {
    extern __shared__ float sm[];
    float* wl1 = sm;             // 4096
    float* wl2 = sm + 4096;      // 4096
    float* wrs = sm + 8192;      // 4096
    float* bsum = sm + 12288;    // 64
    float* w1s = sm + 12352;     // 2048
    float* b1s = sm + 14400;     // 32
    float* w2s = sm + 14432;     // 32
    float* stg = sm + 14464;     // 8 * 192
    float* cst = sm + 14464 + 1536;  // 8 * 64
    int tid = threadIdx.x, lane = tid & 31, w = tid >> 5;
    for (int i = tid; i < 4096; i += 256) {
        wl1[i] = Wl[4096 + i];
        wl2[i] = Wl[8192 + i];
        wrs[i] = Wr[4096 + i] + Wr[8192 + i];
    }
    for (int i = tid; i < 2048; i += 256) w1s[i] = W1[i];
    if (tid < 64) bsum[tid] = bl[64 + tid] + bl[128 + tid];
    if (tid < 32) { b1s[tid] = b1[tid]; w2s[tid] = W2[tid]; }
    int row = blockIdx.x * 8 + w;
    float* S = stg + w * 192;
    if (row < NC) {
        ((float2*)S)[lane] = __half22float2(__ldg(g_aggCm2h + row * 32 + lane));
        ((float2*)(S + 64))[lane] = __half22float2(__ldg(g_aggCrh + row * 32 + lane));
        ((float2*)(S + 128))[lane] = ((const float2*)(g_xc1 + row * 64))[lane];
    }
    __syncthreads();
    if (row >= NC) return;
    float2 acc = make_float2(bsum[2 * lane], bsum[2 * lane + 1]);
#pragma unroll 8
    for (int k = 0; k < 64; k++) {
        float am = S[k], ar = S[64 + k], xk = S[128 + k];
        float2 w1 = ((const float2*)(wl1 + k * 64))[lane];
        float2 w2 = ((const float2*)(wl2 + k * 64))[lane];
        float2 w3 = ((const float2*)(wrs + k * 64))[lane];
        acc.x += am * w1.x + ar * w2.x + xk * w3.x;
        acc.y += am * w1.y + ar * w2.y + xk * w3.y;
    }
    float* C = cst + w * 64;
    C[2 * lane] = fmaxf(acc.x + S[128 + 2 * lane], 0.f);
    C[2 * lane + 1] = fmaxf(acc.y + S[128 + 2 * lane + 1], 0.f);
    __syncwarp();
    float h = b1s[lane];
#pragma unroll 8
    for (int j = 0; j < 64; j++) h += C[j] * w1s[j * 32 + lane];
    float o = fmaxf(h, 0.f) * w2s[lane];
#pragma unroll
    for (int off = 16; off > 0; off >>= 1) o += __shfl_xor_sync(0xffffffffu, o, off);
    if (lane == 0) out[row] = o + __ldg(b2);
}

// ---------------- host launch (R8 schedule + hoisted men-L2 gather) ----------------
extern "C" void kernel_launch(void* const* d_in, const int* in_sizes, int n_in,
                              void* d_out, int out_size) {
    const float* x_news  = (const float*)d_in[0];
    const float* x_comp  = (const float*)d_in[1];
    const int*   e_sim   = (const int*)d_in[2];
    const int*   men_src = (const int*)d_in[3];
    const int*   men_dst = (const int*)d_in[4];
    const int*   e_rel   = (const int*)d_in[5];
    const float* nw_W = (const float*)d_in[6];
    const float* nw_b = (const float*)d_in[7];
    const float* cw_W = (const float*)d_in[8];
    const float* cw_b = (const float*)d_in[9];
    const float* n1n_g = (const float*)d_in[10];
    const float* n1n_b = (const float*)d_in[11];
    const float* n1c_g = (const float*)d_in[12];
    const float* n1c_b = (const float*)d_in[13];
    const float* c1_Wl = (const float*)d_in[14];
    const float* c1_bl = (const float*)d_in[15];
    const float* c1_Wr = (const float*)d_in[16];
    const float* c2_Wl = (const float*)d_in[17];
    const float* c2_bl = (const float*)d_in[18];
    const float* c2_Wr = (const float*)d_in[19];
    const float* cls_W1 = (const float*)d_in[20];
    const float* cls_b1 = (const float*)d_in[21];
    const float* cls_W2 = (const float*)d_in[22];
    const float* cls_b2 = (const float*)d_in[23];
    float* out = (float*)d_out;

    const int Es = in_sizes[2] / 2;
    const int Em = in_sizes[3];
    const int Er = in_sizes[5] / 2;
    const int* es_src = e_sim;
    const int* es_dst = e_sim + Es;
    const int* rl_src = e_rel;
    const int* rl_dst = e_rel + Er;

    __half2 *p_xn0h, *p_xn1h, *p_xc0h, *p_xc1h, *p_aggNh, *p_aggCmh, *p_aggCm2h, *p_aggCrh;
    int *p_bufS, *p_bufM, *p_bufR, *p_cntS, *p_cntM, *p_cntR;
    cudaGetSymbolAddress((void**)&p_xn0h, g_xn0h);
    cudaGetSymbolAddress((void**)&p_xn1h, g_xn1h);
    cudaGetSymbolAddress((void**)&p_xc0h, g_xc0h);
    cudaGetSymbolAddress((void**)&p_xc1h, g_xc1h);
    cudaGetSymbolAddress((void**)&p_aggNh, g_aggNh);
    cudaGetSymbolAddress((void**)&p_aggCmh, g_aggCmh);
    cudaGetSymbolAddress((void**)&p_aggCm2h, g_aggCm2h);
    cudaGetSymbolAddress((void**)&p_aggCrh, g_aggCrh);
    cudaGetSymbolAddress((void**)&p_bufS, g_bufS);
    cudaGetSymbolAddress((void**)&p_bufM, g_bufM);
    cudaGetSymbolAddress((void**)&p_bufR, g_bufR);
    cudaGetSymbolAddress((void**)&p_cntS, g_cntS);
    cudaGetSymbolAddress((void**)&p_cntM, g_cntM);
    cudaGetSymbolAddress((void**)&p_cntR, g_cntR);

    const int GEMM_SMEM = (8192 + 128) * 4;                       // 33280
    const int NU_SMEM = 2 * 128 * 72 * 2 + 2 * 64 * 72 * 2;       // 55296
    cudaFuncSetAttribute(news_update_kernel, cudaFuncAttributeMaxDynamicSharedMemorySize, NU_SMEM);
    cudaFuncSetAttribute(comp1_kernel, cudaFuncAttributeMaxDynamicSharedMemorySize, 56000);
    cudaFuncSetAttribute(compF_kernel, cudaFuncAttributeMaxDynamicSharedMemorySize, 66048);

    // ONE extra stream + 4 events (the budget proven to pass the teardown check)
    cudaStream_t s2;
    cudaStreamCreateWithFlags(&s2, cudaStreamNonBlocking);
    cudaEvent_t e0, eA, eB, e3;
    cudaEventCreateWithFlags(&e0, cudaEventDisableTiming);
    cudaEventCreateWithFlags(&eA, cudaEventDisableTiming);
    cudaEventCreateWithFlags(&eB, cudaEventDisableTiming);
    cudaEventCreateWithFlags(&e3, cudaEventDisableTiming);

    // fork s2 from the capture origin stream
    cudaEventRecord(e0, 0);
    cudaStreamWaitEvent(s2, e0, 0);

    // branch 0 (origin): adjacency build
    zero_cnt_kernel<<<(NN + 255) / 256, 256>>>();
    fill_kernel<<<(Es + 255) / 256, 256>>>(es_src, es_dst, men_src, men_dst,
                                           rl_src, rl_dst, Es, Em, Er);
    cudaEventRecord(eA, 0);

    // branch s2: input projections (independent of adjacency)
    gemm_news0_kernel<<<(NN + 127) / 128, 256, GEMM_SMEM, s2>>>(x_news, nw_W, nw_b);
    comp0_kernel<<<(NC + 7) / 8, 256, 0, s2>>>(x_comp, cw_W, cw_b);
    cudaEventRecord(eB, s2);

    // cross-join: each branch needs the other's outputs
    cudaStreamWaitEvent(0, eB, 0);
    cudaStreamWaitEvent(s2, eA, 0);

    // branch 0: big news gather + news update, then the HOISTED layer-2 mentions gather.
    // menL2 depends only on xn1h (origin) + bufM (fill) and writes the SEPARATE aggCm2h,
    // so it runs before the e3 join, overlapping s2's comp1/relL2 tail.
    gatherh_kernel<<<(NN * 32 + 255) / 256, 256>>>(p_xn0h, p_bufS, p_cntS, p_aggNh, NN, CAP_SIM);
    news_update_kernel<<<(NN + 127) / 128, 256, NU_SMEM>>>(c1_Wl, c1_bl, c1_Wr, n1n_g, n1n_b);
    gatherh_kernel<<<(NC * 32 + 255) / 256, 256>>>(p_xn1h, p_bufM, p_cntM, p_aggCm2h, NC, CAP_MEN);

    // branch s2: company gathers + company update + layer-2 rel gather (overlaps news chain)
    gatherh_kernel<<<(NC * 32 + 255) / 256, 256, 0, s2>>>(p_xn0h, p_bufM, p_cntM, p_aggCmh, NC, CAP_MEN);
    gatherh_kernel<<<(NC * 32 + 255) / 256, 256, 0, s2>>>(p_xc0h, p_bufR, p_cntR, p_aggCrh, NC, CAP_REL);
    comp1_kernel<<<(NC + 7) / 8, 256, 56000, s2>>>(c1_Wl, c1_bl, c1_Wr, n1c_g, n1c_b);
    gatherh_kernel<<<(NC * 32 + 255) / 256, 256, 0, s2>>>(p_xc1h, p_bufR, p_cntR, p_aggCrh, NC, CAP_REL);
    cudaEventRecord(e3, s2);

    // join and finish on origin stream
    cudaStreamWaitEvent(0, e3, 0);
    compF_kernel<<<(NC + 7) / 8, 256, 66048>>>(c2_Wl, c2_bl, c2_Wr, cls_W1, cls_b1, cls_W2, cls_b2, out);
}